// round 4
// baseline (speedup 1.0000x reference)
#include <cuda_runtime.h>
#include <math.h>

#define NB 32
#define Wd 512
#define Hd 512
#define SEG (Hd*Wd)              // 262144 per image
#define NTOT (NB*SEG)            // 8388608
#define TPB 256
#define IPT 16
#define BLK_ITEMS (TPB*IPT)      // 4096
#define NBLOCKS (NTOT/BLK_ITEMS) // 2048
#define BLKS_PER_SEG (SEG/BLK_ITEMS) // 64

// ---------------- scratch (static device globals; no allocation) -------------
__device__ unsigned g_keysA[NTOT];
__device__ unsigned g_keysB[NTOT];
__device__ unsigned g_bh[4][NBLOCKS*256];   // per-pass per-block digit histograms
__device__ unsigned g_bb[NBLOCKS*256];      // per-block per-digit absolute base (this pass)
__device__ unsigned g_chunkPos[NBLOCKS];    // positives per 4096-chunk of final sorted array
__device__ unsigned g_chunkOff[NBLOCKS];    // exclusive prefix within segment
__device__ double g_bce, g_bnd;
__device__ double g_pt[NB], g_pd[NB], g_gts[NB];
__device__ double g_lov[NB];

// ---------------- helpers ----------------------------------------------------
__device__ __forceinline__ float warpReduceF(float v) {
    #pragma unroll
    for (int o = 16; o; o >>= 1) v += __shfl_down_sync(0xFFFFFFFFu, v, o);
    return v;
}

__device__ __forceinline__ float blockReduceF(float v) {
    __shared__ float s[8];
    int lane = threadIdx.x & 31, wid = threadIdx.x >> 5;
    v = warpReduceF(v);
    if (lane == 0) s[wid] = v;
    __syncthreads();
    v = (threadIdx.x < 8) ? s[threadIdx.x] : 0.f;
    if (wid == 0) v = warpReduceF(v);
    __syncthreads();
    return v;  // valid on thread 0
}

// 256-thread exclusive scan (one int per thread)
__device__ __forceinline__ int blockExclScanI(int v) {
    int lane = threadIdx.x & 31, wid = threadIdx.x >> 5;
    int inc = v;
    #pragma unroll
    for (int o = 1; o < 32; o <<= 1) {
        int n = __shfl_up_sync(0xFFFFFFFFu, inc, o);
        if (lane >= o) inc += n;
    }
    __shared__ int ws[8];
    if (lane == 31) ws[wid] = inc;
    __syncthreads();
    if (threadIdx.x < 8) {
        int s = ws[threadIdx.x]; int i2 = s;
        #pragma unroll
        for (int o = 1; o < 8; o <<= 1) {
            int n = __shfl_up_sync(0xFFu, i2, o);
            if ((int)threadIdx.x >= o) i2 += n;
        }
        ws[threadIdx.x] = i2 - s;
    }
    __syncthreads();
    int r = inc - v + ws[wid];
    __syncthreads();
    return r;
}

// descending-float order == ascending-uint order; label y in mantissa LSB
__device__ __forceinline__ unsigned encodeKey(float e, int y) {
    unsigned u = (__float_as_uint(e) & ~1u) | (unsigned)y;
    unsigned o = (u & 0x80000000u) ? ~u : (u ^ 0x80000000u);
    return ~o;
}
__device__ __forceinline__ unsigned decodeBits(unsigned key) {
    unsigned o = ~key;
    return (o & 0x80000000u) ? (o ^ 0x80000000u) : ~o;
}

// ---------------- kernels ----------------------------------------------------
__global__ void k_init() {
    int t = blockIdx.x * blockDim.x + threadIdx.x;
    int n = 3*NBLOCKS*256;  // zero g_bh[1..3]
    for (int i = t; i < n; i += gridDim.x * blockDim.x) g_bh[1][i] = 0;
    if (t < NBLOCKS) g_chunkPos[t] = 0;
    if (t < NB) { g_pt[t] = 0.0; g_pd[t] = 0.0; g_gts[t] = 0.0; g_lov[t] = 0.0; }
    if (t == NB) { g_bce = 0.0; g_bnd = 0.0; }
}

// Fused: BCE + boundary BCE + Dice sums + key build + pass-0 per-block histogram
__global__ void k_main(const float* __restrict__ logits, const float* __restrict__ tgt) {
    int blk = blockIdx.x;
    int seg = blk / BLKS_PER_SEG;
    int base = blk * BLK_ITEMS;
    int t = threadIdx.x;

    __shared__ unsigned sh_hist[256];
    sh_hist[t] = 0;
    __syncthreads();

    float accBce = 0.f, accBnd = 0.f, accPt = 0.f, accPd = 0.f, accY = 0.f;

    #pragma unroll
    for (int k = 0; k < IPT; k++) {
        int idx = base + t + k*TPB;
        float x = logits[idx];
        float y = tgt[idx];
        float ax = fabsf(x);
        float bce = fmaxf(x, 0.f) - x*y + log1pf(expf(-ax));
        float p = 1.f / (1.f + expf(-x));

        // 3x3 boundary: count of ones in zero-padded SAME window; edge iff 1..8
        int pos = idx - seg*SEG;
        int h = pos >> 9, w = pos & 511;
        int cnt = 0;
        #pragma unroll
        for (int dh = -1; dh <= 1; dh++) {
            int hh = h + dh; if (hh < 0 || hh >= Hd) continue;
            #pragma unroll
            for (int dw = -1; dw <= 1; dw++) {
                int ww = w + dw; if (ww < 0 || ww >= Wd) continue;
                cnt += (int)__ldg(&tgt[idx + dh*Wd + dw]);
            }
        }
        float wt = (cnt >= 1 && cnt <= 8) ? 3.0f : 1.0f;

        accBce += bce;
        accBnd += bce * wt;
        accPt  += p * y;
        accPd  += p + y;
        accY   += y;

        int yi = (int)y;
        float e = fmaf(-x, 2.f*y - 1.f, 1.f);   // 1 - x*sign
        unsigned key = encodeKey(e, yi);
        g_keysA[idx] = key;
        atomicAdd(&sh_hist[key & 255u], 1u);
    }
    __syncthreads();
    g_bh[0][blk*256 + t] = sh_hist[t];

    float r;
    r = blockReduceF(accBce); if (t == 0) atomicAdd(&g_bce, (double)r);
    r = blockReduceF(accBnd); if (t == 0) atomicAdd(&g_bnd, (double)r);
    r = blockReduceF(accPt);  if (t == 0) atomicAdd(&g_pt[seg], (double)r);
    r = blockReduceF(accPd);  if (t == 0) atomicAdd(&g_pd[seg], (double)r);
    r = blockReduceF(accY);   if (t == 0) atomicAdd(&g_gts[seg], (double)r);
}

// Per pass: absolute base for every (block, digit), in strict block order (stable).
// grid = NB (one block per image), block = 256 (one thread per digit)
template<int PASS>
__global__ void k_scan() {
    int seg = blockIdx.x, d = threadIdx.x;
    int b0 = seg * BLKS_PER_SEG;
    unsigned total = 0;
    for (int b = 0; b < BLKS_PER_SEG; b++)
        total += g_bh[PASS][(b0 + b)*256 + d];
    unsigned segBase = (unsigned)blockExclScanI((int)total);
    unsigned run = (unsigned)(seg * SEG) + segBase;
    for (int b = 0; b < BLKS_PER_SEG; b++) {
        g_bb[(b0 + b)*256 + d] = run;
        run += g_bh[PASS][(b0 + b)*256 + d];
    }
}

// Stable scatter: stable local rank (match_any rounds) + deterministic block bases.
template<int PASS>
__global__ void k_scatter() {
    const unsigned* __restrict__ in  = (PASS & 1) ? g_keysB : g_keysA;
    unsigned* __restrict__ out       = (PASS & 1) ? g_keysA : g_keysB;

    __shared__ unsigned runCnt[256];   // per-digit count over completed rounds
    __shared__ unsigned Mtag[8*256];   // (round<<16)|cnt per (warp,digit)
    __shared__ unsigned lstart[256];   // block-local exclusive digit starts
    __shared__ unsigned sbase[256];    // absolute global base for this block/digit
    __shared__ unsigned sh_keys[BLK_ITEMS];

    int blk = blockIdx.x, t = threadIdx.x;
    int base = blk * BLK_ITEMS;
    int w = t >> 5, lane = t & 31;
    unsigned laneLow = (1u << lane) - 1u;

    runCnt[t] = 0;
    for (int i = t; i < 8*256; i += TPB) Mtag[i] = 0xFFFF0000u;
    sbase[t] = g_bb[blk*256 + t];
    __syncthreads();

    unsigned keys[IPT];
    unsigned short rankv[IPT];

    #pragma unroll
    for (int j = 0; j < IPT; j++) {
        unsigned key = in[base + j*TPB + t];   // memory order = (j, t)
        keys[j] = key;
        unsigned d = (key >> (8*PASS)) & 255u;
        unsigned mask = __match_any_sync(0xFFFFFFFFu, d);
        unsigned lr = __popc(mask & laneLow);
        unsigned cnt = __popc(mask);
        if (lr == 0) Mtag[w*256 + d] = ((unsigned)j << 16) | cnt;
        __syncthreads();
        unsigned pre = runCnt[d];
        for (int ww = 0; ww < w; ww++) {
            unsigned v = Mtag[ww*256 + d];
            if ((v >> 16) == (unsigned)j) pre += v & 0xFFFFu;
        }
        rankv[j] = (unsigned short)(pre + lr);
        __syncthreads();
        if (lr == 0) atomicAdd(&runCnt[d], cnt);
    }
    __syncthreads();

    // block-local digit starts
    unsigned tot = runCnt[t];
    unsigned ex = (unsigned)blockExclScanI((int)tot);
    lstart[t] = ex;
    __syncthreads();

    // stage grouped (stable within digit)
    #pragma unroll
    for (int j = 0; j < IPT; j++) {
        unsigned d = (keys[j] >> (8*PASS)) & 255u;
        sh_keys[lstart[d] + rankv[j]] = keys[j];
    }
    __syncthreads();

    // coalesced write-out + feed next-pass per-block histogram
    #pragma unroll
    for (int j = 0; j < IPT; j++) {
        int sp = j*TPB + t;
        unsigned key = sh_keys[sp];
        unsigned d = (key >> (8*PASS)) & 255u;
        unsigned pos = sbase[d] + ((unsigned)sp - lstart[d]);
        out[pos] = key;
        if (PASS < 3) {
            unsigned dnext = (key >> (8*(PASS+1))) & 255u;
            atomicAdd(&g_bh[PASS+1][(pos >> 12)*256 + dnext], 1u);
        } else {
            unsigned y = decodeBits(key) & 1u;
            if (y) atomicAdd(&g_chunkPos[pos >> 12], 1u);
        }
    }
}

__global__ void k_chunkscan() {
    int s = threadIdx.x;  // one thread per image
    if (s >= NB) return;
    unsigned run = 0;
    for (int c = 0; c < BLKS_PER_SEG; c++) {
        g_chunkOff[s*BLKS_PER_SEG + c] = run;
        run += g_chunkPos[s*BLKS_PER_SEG + c];
    }
}

__global__ void k_lovasz() {
    int blk = blockIdx.x, t = threadIdx.x;
    int seg = blk / BLKS_PER_SEG;
    int base = blk * BLK_ITEMS;

    unsigned u[IPT]; int yv[IPT];
    const uint4* p4 = (const uint4*)(g_keysA + base + t*IPT);
    int lsum = 0;
    #pragma unroll
    for (int q = 0; q < IPT/4; q++) {
        uint4 kk = p4[q];
        unsigned arr[4] = {kk.x, kk.y, kk.z, kk.w};
        #pragma unroll
        for (int r = 0; r < 4; r++) {
            unsigned uu = decodeBits(arr[r]);
            u[q*4 + r] = uu;
            yv[q*4 + r] = (int)(uu & 1u);
            lsum += (int)(uu & 1u);
        }
    }

    int excl = blockExclScanI(lsum);
    float gts = (float)g_gts[seg];
    float P = (float)(g_chunkOff[blk] + (unsigned)excl); // positives strictly before first item
    int pos0 = (blk % BLKS_PER_SEG) * BLK_ITEMS + t*IPT; // 0-based rank in segment

    float acc = 0.f;
    #pragma unroll
    for (int j = 0; j < IPT; j++) {
        float e = __uint_as_float(u[j]);
        int y = yv[j];
        if (e > 0.f) {
            float Uprev = gts + (float)(pos0 + j) - P;  // union before this element
            float grad = y ? (1.0f / Uprev)
                           : ((gts - P) / (Uprev * (Uprev + 1.0f)));
            acc += e * grad;
        }
        P += (float)y;
    }
    float r = blockReduceF(acc);
    if (t == 0) atomicAdd(&g_lov[seg], (double)r);
}

__global__ void k_final(float* out, int out_size) {
    if (threadIdx.x == 0 && blockIdx.x == 0) {
        double dice = 0.0;
        for (int b = 0; b < NB; b++) dice += (2.0 * g_pt[b]) / (g_pd[b] + 1e-7);
        double lov = 0.0;
        for (int b = 0; b < NB; b++) lov += g_lov[b];
        double loss = 0.3 * (g_bce / (double)NTOT)
                    + 0.3 * (1.0 - dice / (double)NB)
                    + 0.2 * (g_bnd / (double)NTOT)
                    + 0.2 * (lov / (double)NB);
        for (int i = 0; i < out_size; i++) out[i] = (float)loss;
    }
}

// ---------------- launch ------------------------------------------------------
extern "C" void kernel_launch(void* const* d_in, const int* in_sizes, int n_in,
                              void* d_out, int out_size) {
    const float* logits = (const float*)d_in[0];
    const float* tgt    = (const float*)d_in[1];
    float* out = (float*)d_out;

    k_init<<<6144, 256>>>();
    k_main<<<NBLOCKS, TPB>>>(logits, tgt);
    k_scan<0><<<NB, 256>>>();
    k_scatter<0><<<NBLOCKS, TPB>>>();
    k_scan<1><<<NB, 256>>>();
    k_scatter<1><<<NBLOCKS, TPB>>>();
    k_scan<2><<<NB, 256>>>();
    k_scatter<2><<<NBLOCKS, TPB>>>();
    k_scan<3><<<NB, 256>>>();
    k_scatter<3><<<NBLOCKS, TPB>>>();
    k_chunkscan<<<1, 32>>>();
    k_lovasz<<<NBLOCKS, TPB>>>();
    k_final<<<1, 32>>>(out, out_size);
}

// round 5
// speedup vs baseline: 2.3867x; 2.3867x over previous
#include <cuda_runtime.h>
#include <math.h>

#define NB 32
#define Wd 512
#define Hd 512
#define SEG (Hd*Wd)              // 262144 per image
#define NTOT (NB*SEG)            // 8388608
#define TPB 256
#define IPT 16
#define BLK_ITEMS (TPB*IPT)      // 4096
#define NBLOCKS (NTOT/BLK_ITEMS) // 2048
#define BLKS_PER_SEG (SEG/BLK_ITEMS) // 64

// ---------------- scratch (static device globals; no allocation) -------------
__device__ unsigned g_keysA[NTOT];
__device__ unsigned g_keysB[NTOT];
__device__ unsigned g_bh[NB*256*64];     // per-(seg,digit): 64 per-block counts, contiguous
__device__ unsigned g_bb[NBLOCKS*256];   // per-block per-digit absolute base (current pass)
__device__ unsigned g_chunkPos[NBLOCKS];
__device__ unsigned g_chunkOff[NBLOCKS];
__device__ double g_bce, g_bnd;
__device__ double g_pt[NB], g_pd[NB], g_gts[NB];
__device__ double g_lov[NB];

// ---------------- helpers ----------------------------------------------------
__device__ __forceinline__ float warpReduceF(float v) {
    #pragma unroll
    for (int o = 16; o; o >>= 1) v += __shfl_down_sync(0xFFFFFFFFu, v, o);
    return v;
}

__device__ __forceinline__ float blockReduceF(float v) {
    __shared__ float s[8];
    int lane = threadIdx.x & 31, wid = threadIdx.x >> 5;
    v = warpReduceF(v);
    if (lane == 0) s[wid] = v;
    __syncthreads();
    v = (threadIdx.x < 8) ? s[threadIdx.x] : 0.f;
    if (wid == 0) v = warpReduceF(v);
    __syncthreads();
    return v;  // valid on thread 0
}

// 256-thread exclusive scan (one int per thread)
__device__ __forceinline__ int blockExclScanI(int v) {
    int lane = threadIdx.x & 31, wid = threadIdx.x >> 5;
    int inc = v;
    #pragma unroll
    for (int o = 1; o < 32; o <<= 1) {
        int n = __shfl_up_sync(0xFFFFFFFFu, inc, o);
        if (lane >= o) inc += n;
    }
    __shared__ int ws[8];
    if (lane == 31) ws[wid] = inc;
    __syncthreads();
    if (threadIdx.x < 8) {
        int s = ws[threadIdx.x]; int i2 = s;
        #pragma unroll
        for (int o = 1; o < 8; o <<= 1) {
            int n = __shfl_up_sync(0xFFu, i2, o);
            if ((int)threadIdx.x >= o) i2 += n;
        }
        ws[threadIdx.x] = i2 - s;
    }
    __syncthreads();
    int r = inc - v + ws[wid];
    __syncthreads();
    return r;
}

// descending-float order == ascending-uint order; label y in mantissa LSB
__device__ __forceinline__ unsigned encodeKey(float e, int y) {
    unsigned u = (__float_as_uint(e) & ~1u) | (unsigned)y;
    unsigned o = (u & 0x80000000u) ? ~u : (u ^ 0x80000000u);
    return ~o;
}
__device__ __forceinline__ unsigned decodeBits(unsigned key) {
    unsigned o = ~key;
    return (o & 0x80000000u) ? (o ^ 0x80000000u) : ~o;
}

// ---------------- kernels ----------------------------------------------------
__global__ void k_init() {
    int t = blockIdx.x * blockDim.x + threadIdx.x;
    if (t < NBLOCKS) g_chunkPos[t] = 0;
    if (t < NB) { g_pt[t] = 0.0; g_pd[t] = 0.0; g_gts[t] = 0.0; g_lov[t] = 0.0; }
    if (t == NB) { g_bce = 0.0; g_bnd = 0.0; }
}

// Fused: BCE + boundary BCE + Dice sums + key build + pass-0 (shift 8) histogram.
// Each thread owns 16 CONTIGUOUS pixels (one row span); stencil via float4 loads.
__global__ __launch_bounds__(TPB) void k_main(const float* __restrict__ logits,
                                              const float* __restrict__ tgt) {
    int blk = blockIdx.x, t = threadIdx.x;
    int seg = blk >> 6;
    int base = blk * BLK_ITEMS;

    __shared__ unsigned sh_hist[256];
    __shared__ unsigned sh_keys[BLK_ITEMS];
    sh_hist[t] = 0;
    __syncthreads();

    float aB = 0.f, aW = 0.f, aPt = 0.f, aPd = 0.f, aY = 0.f;

    int q0 = base + t * 16;           // first pixel of this thread (global index)
    int pos0 = q0 - seg * SEG;
    int h = pos0 >> 9;
    int w0 = pos0 & 511;
    bool hasTop = (h > 0), hasBot = (h < Hd - 1);

    const float4* lg4 = (const float4*)logits;
    const float4* tg4 = (const float4*)tgt;

    #pragma unroll
    for (int c = 0; c < 4; c++) {
        int p = q0 + c * 4;
        int w = w0 + c * 4;
        float4 lx = lg4[p >> 2];

        float rv[3][6];
        #pragma unroll
        for (int r = 0; r < 3; r++) {
            int dr = r - 1;
            bool rowok = (dr == 0) || (dr < 0 ? hasTop : hasBot);
            int rp = p + dr * Wd;
            float4 cv = rowok ? tg4[rp >> 2] : make_float4(0.f, 0.f, 0.f, 0.f);
            rv[r][1] = cv.x; rv[r][2] = cv.y; rv[r][3] = cv.z; rv[r][4] = cv.w;
            rv[r][0] = (rowok && w > 0)        ? __ldg(&tgt[rp - 1]) : 0.f;
            rv[r][5] = (rowok && w + 4 < Wd)   ? __ldg(&tgt[rp + 4]) : 0.f;
        }

        float xs[4] = {lx.x, lx.y, lx.z, lx.w};
        #pragma unroll
        for (int i = 0; i < 4; i++) {
            float x = xs[i];
            float y = rv[1][i + 1];
            float ax = fabsf(x);
            float bce = fmaxf(x, 0.f) - x * y + log1pf(expf(-ax));
            float pr = 1.f / (1.f + expf(-x));
            float cnt = rv[0][i] + rv[0][i+1] + rv[0][i+2]
                      + rv[1][i] + rv[1][i+1] + rv[1][i+2]
                      + rv[2][i] + rv[2][i+1] + rv[2][i+2];
            float wt = (cnt > 0.5f && cnt < 8.5f) ? 3.0f : 1.0f;

            aB += bce; aW += bce * wt; aPt += pr * y; aPd += pr + y; aY += y;

            unsigned key = encodeKey(fmaf(-x, 2.f*y - 1.f, 1.f), (int)y);
            sh_keys[t * 16 + c * 4 + i] = key;
            atomicAdd(&sh_hist[(key >> 8) & 255u], 1u);
        }
    }
    __syncthreads();

    // coalesced key write-out
    #pragma unroll
    for (int j = 0; j < IPT; j++)
        g_keysA[base + j*TPB + t] = sh_keys[j*TPB + t];

    g_bh[(seg*256 + t)*64 + (blk & 63)] = sh_hist[t];

    float r;
    r = blockReduceF(aB);  if (t == 0) atomicAdd(&g_bce, (double)r);
    r = blockReduceF(aW);  if (t == 0) atomicAdd(&g_bnd, (double)r);
    r = blockReduceF(aPt); if (t == 0) atomicAdd(&g_pt[seg], (double)r);
    r = blockReduceF(aPd); if (t == 0) atomicAdd(&g_pd[seg], (double)r);
    r = blockReduceF(aY);  if (t == 0) atomicAdd(&g_gts[seg], (double)r);
}

// Streaming per-block histogram for a pass (reads current buffer)
template<int SHIFT, bool SRC_A>
__global__ __launch_bounds__(TPB) void k_hist() {
    const unsigned* __restrict__ in = SRC_A ? g_keysA : g_keysB;
    __shared__ unsigned sh[256];
    int blk = blockIdx.x, t = threadIdx.x;
    int seg = blk >> 6;
    sh[t] = 0;
    __syncthreads();
    const uint4* in4 = (const uint4*)(in + blk * BLK_ITEMS);
    #pragma unroll
    for (int j = 0; j < IPT/4; j++) {
        uint4 k = in4[j*TPB + t];
        atomicAdd(&sh[(k.x >> SHIFT) & 255u], 1u);
        atomicAdd(&sh[(k.y >> SHIFT) & 255u], 1u);
        atomicAdd(&sh[(k.z >> SHIFT) & 255u], 1u);
        atomicAdd(&sh[(k.w >> SHIFT) & 255u], 1u);
    }
    __syncthreads();
    g_bh[(seg*256 + t)*64 + (blk & 63)] = sh[t];
}

// Per-pass scan: absolute base for every (block,digit), strict block order.
// grid = NB, block = 256 (thread = digit)
__global__ void k_scan() {
    int seg = blockIdx.x, d = threadIdx.x;
    const uint4* src = (const uint4*)&g_bh[(seg*256 + d)*64];
    unsigned tot = 0;
    #pragma unroll
    for (int q = 0; q < 16; q++) {
        uint4 hh = src[q];
        tot += hh.x + hh.y + hh.z + hh.w;
    }
    unsigned ex = (unsigned)blockExclScanI((int)tot);
    unsigned run = (unsigned)(seg * SEG) + ex;
    int b0 = seg * BLKS_PER_SEG;
    #pragma unroll
    for (int q = 0; q < 16; q++) {
        uint4 hh = src[q];
        g_bb[(b0 + q*4 + 0)*256 + d] = run; run += hh.x;
        g_bb[(b0 + q*4 + 1)*256 + d] = run; run += hh.y;
        g_bb[(b0 + q*4 + 2)*256 + d] = run; run += hh.z;
        g_bb[(b0 + q*4 + 3)*256 + d] = run; run += hh.w;
    }
}

// Stable scatter: warp-private stable ranking (no block syncs in rounds).
// Warp w owns items [w*512, (w+1)*512) of the block, lane order = memory order.
template<int SHIFT, bool IN_A, bool DO_CHUNK>
__global__ __launch_bounds__(TPB) void k_scatter() {
    const unsigned* __restrict__ in  = IN_A ? g_keysA : g_keysB;
    unsigned* __restrict__ out       = IN_A ? g_keysB : g_keysA;

    __shared__ unsigned runCnt[8*256];  // per-warp digit counters -> warp starts
    __shared__ unsigned lstart[256];    // block-local digit starts
    __shared__ unsigned sbase[256];     // absolute global base for this block
    __shared__ unsigned sh_keys[BLK_ITEMS];

    int blk = blockIdx.x, t = threadIdx.x;
    int w = t >> 5, lane = t & 31;
    unsigned laneLow = (1u << lane) - 1u;
    int base = blk * BLK_ITEMS;

    sbase[t] = g_bb[blk*256 + t];
    #pragma unroll
    for (int i = 0; i < 8; i++) runCnt[i*256 + t] = 0;
    __syncthreads();

    unsigned keys[IPT];
    unsigned short rk[IPT];
    int wbase = base + w * 512;

    #pragma unroll
    for (int j = 0; j < IPT; j++) {
        unsigned key = in[wbase + j*32 + lane];
        keys[j] = key;
        unsigned d = (key >> SHIFT) & 255u;
        unsigned mask = __match_any_sync(0xFFFFFFFFu, d);
        unsigned lr = __popc(mask & laneLow);
        unsigned pre = runCnt[w*256 + d];
        rk[j] = (unsigned short)(pre + lr);
        __syncwarp();
        if (lr == 0) runCnt[w*256 + d] = pre + __popc(mask);
        __syncwarp();
    }
    __syncthreads();

    // block-level digit offsets (thread t = digit)
    unsigned c[8], tot = 0;
    #pragma unroll
    for (int i = 0; i < 8; i++) { c[i] = runCnt[i*256 + t]; tot += c[i]; }
    unsigned ex = (unsigned)blockExclScanI((int)tot);
    lstart[t] = ex;
    unsigned run = ex;
    #pragma unroll
    for (int i = 0; i < 8; i++) { runCnt[i*256 + t] = run; run += c[i]; }
    __syncthreads();

    // stage grouped (stable within digit)
    #pragma unroll
    for (int j = 0; j < IPT; j++) {
        unsigned d = (keys[j] >> SHIFT) & 255u;
        sh_keys[runCnt[w*256 + d] + (unsigned)rk[j]] = keys[j];
    }
    __syncthreads();

    // coalesced-run write-out
    #pragma unroll
    for (int j = 0; j < IPT; j++) {
        int sp = j*TPB + t;
        unsigned key = sh_keys[sp];
        unsigned d = (key >> SHIFT) & 255u;
        unsigned pos = sbase[d] + ((unsigned)sp - lstart[d]);
        out[pos] = key;
        if (DO_CHUNK) {
            unsigned y = decodeBits(key) & 1u;
            unsigned chunk = pos >> 12;
            unsigned vm = y ? chunk : (0x80000000u | (unsigned)lane);
            unsigned mm = __match_any_sync(0xFFFFFFFFu, vm);
            if (y && (mm & laneLow) == 0) atomicAdd(&g_chunkPos[chunk], __popc(mm));
        }
    }
}

__global__ void k_chunkscan() {
    int s = threadIdx.x;  // one thread per image
    if (s >= NB) return;
    unsigned run = 0;
    for (int c = 0; c < BLKS_PER_SEG; c++) {
        g_chunkOff[s*BLKS_PER_SEG + c] = run;
        run += g_chunkPos[s*BLKS_PER_SEG + c];
    }
}

__global__ __launch_bounds__(TPB) void k_lovasz() {
    int blk = blockIdx.x, t = threadIdx.x;
    int seg = blk / BLKS_PER_SEG;
    int base = blk * BLK_ITEMS;

    unsigned u[IPT]; int yv[IPT];
    const uint4* p4 = (const uint4*)(g_keysB + base + t*IPT);
    int lsum = 0;
    #pragma unroll
    for (int q = 0; q < IPT/4; q++) {
        uint4 kk = p4[q];
        unsigned arr[4] = {kk.x, kk.y, kk.z, kk.w};
        #pragma unroll
        for (int r = 0; r < 4; r++) {
            unsigned uu = decodeBits(arr[r]);
            u[q*4 + r] = uu;
            yv[q*4 + r] = (int)(uu & 1u);
            lsum += (int)(uu & 1u);
        }
    }

    int excl = blockExclScanI(lsum);
    float gts = (float)g_gts[seg];
    float P = (float)(g_chunkOff[blk] + (unsigned)excl); // positives strictly before
    int pos0 = (blk % BLKS_PER_SEG) * BLK_ITEMS + t*IPT;

    float acc = 0.f;
    #pragma unroll
    for (int j = 0; j < IPT; j++) {
        float e = __uint_as_float(u[j]);
        int y = yv[j];
        if (e > 0.f) {
            float Uprev = gts + (float)(pos0 + j) - P;
            float grad = y ? (1.0f / Uprev)
                           : ((gts - P) / (Uprev * (Uprev + 1.0f)));
            acc += e * grad;
        }
        P += (float)y;
    }
    float r = blockReduceF(acc);
    if (t == 0) atomicAdd(&g_lov[seg], (double)r);
}

__global__ void k_final(float* out, int out_size) {
    if (threadIdx.x == 0 && blockIdx.x == 0) {
        double dice = 0.0;
        for (int b = 0; b < NB; b++) dice += (2.0 * g_pt[b]) / (g_pd[b] + 1e-7);
        double lov = 0.0;
        for (int b = 0; b < NB; b++) lov += g_lov[b];
        double loss = 0.3 * (g_bce / (double)NTOT)
                    + 0.3 * (1.0 - dice / (double)NB)
                    + 0.2 * (g_bnd / (double)NTOT)
                    + 0.2 * (lov / (double)NB);
        for (int i = 0; i < out_size; i++) out[i] = (float)loss;
    }
}

// ---------------- launch ------------------------------------------------------
extern "C" void kernel_launch(void* const* d_in, const int* in_sizes, int n_in,
                              void* d_out, int out_size) {
    const float* logits = (const float*)d_in[0];
    const float* tgt    = (const float*)d_in[1];
    float* out = (float*)d_out;

    k_init<<<8, 256>>>();
    k_main<<<NBLOCKS, TPB>>>(logits, tgt);

    // pass 1: shift 8, A -> B (hist from k_main)
    k_scan<<<NB, 256>>>();
    k_scatter<8, true, false><<<NBLOCKS, TPB>>>();

    // pass 2: shift 16, B -> A
    k_hist<16, false><<<NBLOCKS, TPB>>>();
    k_scan<<<NB, 256>>>();
    k_scatter<16, false, false><<<NBLOCKS, TPB>>>();

    // pass 3: shift 24, A -> B (+ per-chunk positive counts)
    k_hist<24, true><<<NBLOCKS, TPB>>>();
    k_scan<<<NB, 256>>>();
    k_scatter<24, true, true><<<NBLOCKS, TPB>>>();

    k_chunkscan<<<1, 32>>>();
    k_lovasz<<<NBLOCKS, TPB>>>();
    k_final<<<1, 32>>>(out, out_size);
}

// round 8
// speedup vs baseline: 3.4983x; 1.4658x over previous
#include <cuda_runtime.h>
#include <math.h>

#define NB 32
#define Wd 512
#define Hd 512
#define SEG (Hd*Wd)              // 262144 per image
#define NTOT (NB*SEG)            // 8388608
#define TPB 256
#define IPT 16
#define BLK_ITEMS (TPB*IPT)      // 4096
#define NBLOCKS (NTOT/BLK_ITEMS) // 2048
#define BLKS_PER_SEG (SEG/BLK_ITEMS) // 64

// ---------------- scratch (static device globals; no allocation) -------------
__device__ unsigned g_keysA[NTOT];
__device__ unsigned g_keysB[NTOT];
__device__ unsigned g_bh[NB*256*64];     // per-(seg,digit): 64 per-block counts, contiguous
__device__ unsigned g_bb[NBLOCKS*256];   // per-block per-digit absolute base (current pass)
__device__ unsigned g_chunkPos[NBLOCKS];
__device__ unsigned g_chunkOff[NBLOCKS];
__device__ double g_bce, g_bnd;
__device__ double g_pt[NB], g_pd[NB], g_gts[NB];
__device__ double g_lov[NB];

// ---------------- helpers ----------------------------------------------------
__device__ __forceinline__ float warpReduceF(float v) {
    #pragma unroll
    for (int o = 16; o; o >>= 1) v += __shfl_down_sync(0xFFFFFFFFu, v, o);
    return v;
}

__device__ __forceinline__ float blockReduceF(float v) {
    __shared__ float s[8];
    int lane = threadIdx.x & 31, wid = threadIdx.x >> 5;
    v = warpReduceF(v);
    if (lane == 0) s[wid] = v;
    __syncthreads();
    v = (threadIdx.x < 8) ? s[threadIdx.x] : 0.f;
    if (wid == 0) v = warpReduceF(v);
    __syncthreads();
    return v;  // valid on thread 0
}

// 256-thread exclusive scan (one int per thread)
__device__ __forceinline__ int blockExclScanI(int v) {
    int lane = threadIdx.x & 31, wid = threadIdx.x >> 5;
    int inc = v;
    #pragma unroll
    for (int o = 1; o < 32; o <<= 1) {
        int n = __shfl_up_sync(0xFFFFFFFFu, inc, o);
        if (lane >= o) inc += n;
    }
    __shared__ int ws[8];
    if (lane == 31) ws[wid] = inc;
    __syncthreads();
    if (threadIdx.x < 8) {
        int s = ws[threadIdx.x]; int i2 = s;
        #pragma unroll
        for (int o = 1; o < 8; o <<= 1) {
            int n = __shfl_up_sync(0xFFu, i2, o);
            if ((int)threadIdx.x >= o) i2 += n;
        }
        ws[threadIdx.x] = i2 - s;
    }
    __syncthreads();
    int r = inc - v + ws[wid];
    __syncthreads();
    return r;
}

// descending-float order == ascending-uint order; label y in mantissa LSB
__device__ __forceinline__ unsigned encodeKey(float e, int y) {
    unsigned u = (__float_as_uint(e) & ~1u) | (unsigned)y;
    unsigned o = (u & 0x80000000u) ? ~u : (u ^ 0x80000000u);
    return ~o;
}
__device__ __forceinline__ unsigned decodeBits(unsigned key) {
    unsigned o = ~key;
    return (o & 0x80000000u) ? (o ^ 0x80000000u) : ~o;
}

// ---------------- kernels ----------------------------------------------------
__global__ void k_init() {
    int t = blockIdx.x * blockDim.x + threadIdx.x;
    if (t < NBLOCKS) g_chunkPos[t] = 0;
    if (t < NB) { g_pt[t] = 0.0; g_pd[t] = 0.0; g_gts[t] = 0.0; g_lov[t] = 0.0; }
    if (t == NB) { g_bce = 0.0; g_bnd = 0.0; }
}

// Fused: BCE + boundary BCE + Dice sums + key build + pass-1 (shift 16) histogram.
// Each thread owns 16 CONTIGUOUS pixels (one row span); stencil via float4 loads.
__global__ __launch_bounds__(TPB) void k_main(const float* __restrict__ logits,
                                              const float* __restrict__ tgt) {
    int blk = blockIdx.x, t = threadIdx.x;
    int seg = blk >> 6;
    int base = blk * BLK_ITEMS;

    __shared__ unsigned sh_hist[256];
    __shared__ unsigned sh_keys[BLK_ITEMS];
    sh_hist[t] = 0;
    __syncthreads();

    float aB = 0.f, aW = 0.f, aPt = 0.f, aPd = 0.f, aY = 0.f;

    int q0 = base + t * 16;           // first pixel of this thread (global index)
    int pos0 = q0 - seg * SEG;
    int h = pos0 >> 9;
    int w0 = pos0 & 511;
    bool hasTop = (h > 0), hasBot = (h < Hd - 1);

    const float4* lg4 = (const float4*)logits;
    const float4* tg4 = (const float4*)tgt;

    #pragma unroll
    for (int c = 0; c < 4; c++) {
        int p = q0 + c * 4;
        int w = w0 + c * 4;
        float4 lx = lg4[p >> 2];

        float rv[3][6];
        #pragma unroll
        for (int r = 0; r < 3; r++) {
            int dr = r - 1;
            bool rowok = (dr == 0) || (dr < 0 ? hasTop : hasBot);
            int rp = p + dr * Wd;
            float4 cv = rowok ? tg4[rp >> 2] : make_float4(0.f, 0.f, 0.f, 0.f);
            rv[r][1] = cv.x; rv[r][2] = cv.y; rv[r][3] = cv.z; rv[r][4] = cv.w;
            rv[r][0] = (rowok && w > 0)        ? __ldg(&tgt[rp - 1]) : 0.f;
            rv[r][5] = (rowok && w + 4 < Wd)   ? __ldg(&tgt[rp + 4]) : 0.f;
        }

        float xs[4] = {lx.x, lx.y, lx.z, lx.w};
        #pragma unroll
        for (int i = 0; i < 4; i++) {
            float x = xs[i];
            float y = rv[1][i + 1];
            float ax = fabsf(x);
            float bce = fmaxf(x, 0.f) - x * y + log1pf(expf(-ax));
            float pr = 1.f / (1.f + expf(-x));
            float cnt = rv[0][i] + rv[0][i+1] + rv[0][i+2]
                      + rv[1][i] + rv[1][i+1] + rv[1][i+2]
                      + rv[2][i] + rv[2][i+1] + rv[2][i+2];
            float wt = (cnt > 0.5f && cnt < 8.5f) ? 3.0f : 1.0f;

            aB += bce; aW += bce * wt; aPt += pr * y; aPd += pr + y; aY += y;

            unsigned key = encodeKey(fmaf(-x, 2.f*y - 1.f, 1.f), (int)y);
            sh_keys[t * 16 + c * 4 + i] = key;
            atomicAdd(&sh_hist[(key >> 16) & 255u], 1u);
        }
    }
    __syncthreads();

    // coalesced key write-out
    #pragma unroll
    for (int j = 0; j < IPT; j++)
        g_keysA[base + j*TPB + t] = sh_keys[j*TPB + t];

    g_bh[(seg*256 + t)*64 + (blk & 63)] = sh_hist[t];

    float r;
    r = blockReduceF(aB);  if (t == 0) atomicAdd(&g_bce, (double)r);
    r = blockReduceF(aW);  if (t == 0) atomicAdd(&g_bnd, (double)r);
    r = blockReduceF(aPt); if (t == 0) atomicAdd(&g_pt[seg], (double)r);
    r = blockReduceF(aPd); if (t == 0) atomicAdd(&g_pd[seg], (double)r);
    r = blockReduceF(aY);  if (t == 0) atomicAdd(&g_gts[seg], (double)r);
}

// Streaming per-block histogram for a pass (reads current buffer)
template<int SHIFT, bool SRC_A>
__global__ __launch_bounds__(TPB) void k_hist() {
    const unsigned* __restrict__ in = SRC_A ? g_keysA : g_keysB;
    __shared__ unsigned sh[256];
    int blk = blockIdx.x, t = threadIdx.x;
    int seg = blk >> 6;
    sh[t] = 0;
    __syncthreads();
    const uint4* in4 = (const uint4*)(in + blk * BLK_ITEMS);
    #pragma unroll
    for (int j = 0; j < IPT/4; j++) {
        uint4 k = in4[j*TPB + t];
        atomicAdd(&sh[(k.x >> SHIFT) & 255u], 1u);
        atomicAdd(&sh[(k.y >> SHIFT) & 255u], 1u);
        atomicAdd(&sh[(k.z >> SHIFT) & 255u], 1u);
        atomicAdd(&sh[(k.w >> SHIFT) & 255u], 1u);
    }
    __syncthreads();
    g_bh[(seg*256 + t)*64 + (blk & 63)] = sh[t];
}

// Per-pass scan: absolute base for every (block,digit), strict block order.
// grid = NB, block = 256 (thread = digit)
__global__ void k_scan() {
    int seg = blockIdx.x, d = threadIdx.x;
    const uint4* src = (const uint4*)&g_bh[(seg*256 + d)*64];
    unsigned tot = 0;
    #pragma unroll
    for (int q = 0; q < 16; q++) {
        uint4 hh = src[q];
        tot += hh.x + hh.y + hh.z + hh.w;
    }
    unsigned ex = (unsigned)blockExclScanI((int)tot);
    unsigned run = (unsigned)(seg * SEG) + ex;
    int b0 = seg * BLKS_PER_SEG;
    #pragma unroll
    for (int q = 0; q < 16; q++) {
        uint4 hh = src[q];
        g_bb[(b0 + q*4 + 0)*256 + d] = run; run += hh.x;
        g_bb[(b0 + q*4 + 1)*256 + d] = run; run += hh.y;
        g_bb[(b0 + q*4 + 2)*256 + d] = run; run += hh.z;
        g_bb[(b0 + q*4 + 3)*256 + d] = run; run += hh.w;
    }
}

// Stable scatter. Warp w owns items [w*512,(w+1)*512), lane order = memory order.
// Stable local rank via leader atomicAdd (return value = exclusive base) + shfl
// broadcast. Same-warp smem atomics to one address complete in program order,
// so round order (= memory order) is preserved: stable, and NO barriers in the
// ranking loop -> all rounds pipeline.
template<int SHIFT, bool IN_A, bool DO_CHUNK>
__global__ __launch_bounds__(TPB) void k_scatter() {
    const unsigned* __restrict__ in  = IN_A ? g_keysA : g_keysB;
    unsigned* __restrict__ out       = IN_A ? g_keysB : g_keysA;

    __shared__ unsigned runCnt[8*256];  // per-warp digit counters -> warp starts
    __shared__ unsigned lstart[256];    // block-local digit starts
    __shared__ unsigned sbase[256];     // absolute global base for this block
    __shared__ unsigned sh_keys[BLK_ITEMS];

    int blk = blockIdx.x, t = threadIdx.x;
    int w = t >> 5, lane = t & 31;
    unsigned laneLow = (1u << lane) - 1u;
    int base = blk * BLK_ITEMS;

    sbase[t] = g_bb[blk*256 + t];
    #pragma unroll
    for (int i = 0; i < 8; i++) runCnt[i*256 + t] = 0;
    __syncthreads();

    unsigned keys[IPT];
    unsigned short rk[IPT];
    int wbase = base + w * 512;

    #pragma unroll
    for (int j = 0; j < IPT; j++) {
        unsigned key = in[wbase + j*32 + lane];
        keys[j] = key;
        unsigned d = (key >> SHIFT) & 255u;
        unsigned mask = __match_any_sync(0xFFFFFFFFu, d);
        unsigned lr = __popc(mask & laneLow);
        int leader = __ffs(mask) - 1;
        unsigned pre = 0;
        if (lr == 0) pre = atomicAdd(&runCnt[w*256 + d], __popc(mask));
        pre = __shfl_sync(0xFFFFFFFFu, pre, leader);
        rk[j] = (unsigned short)(pre + lr);
    }
    __syncthreads();

    // block-level digit offsets (thread t = digit)
    unsigned c[8], tot = 0;
    #pragma unroll
    for (int i = 0; i < 8; i++) { c[i] = runCnt[i*256 + t]; tot += c[i]; }
    unsigned ex = (unsigned)blockExclScanI((int)tot);
    lstart[t] = ex;
    unsigned run = ex;
    #pragma unroll
    for (int i = 0; i < 8; i++) { runCnt[i*256 + t] = run; run += c[i]; }
    __syncthreads();

    // stage grouped (stable within digit)
    #pragma unroll
    for (int j = 0; j < IPT; j++) {
        unsigned d = (keys[j] >> SHIFT) & 255u;
        sh_keys[runCnt[w*256 + d] + (unsigned)rk[j]] = keys[j];
    }
    __syncthreads();

    // coalesced-run write-out
    #pragma unroll
    for (int j = 0; j < IPT; j++) {
        int sp = j*TPB + t;
        unsigned key = sh_keys[sp];
        unsigned d = (key >> SHIFT) & 255u;
        unsigned pos = sbase[d] + ((unsigned)sp - lstart[d]);
        out[pos] = key;
        if (DO_CHUNK) {
            unsigned y = decodeBits(key) & 1u;
            unsigned chunk = pos >> 12;
            unsigned vm = y ? chunk : (0x80000000u | (unsigned)lane);
            unsigned mm = __match_any_sync(0xFFFFFFFFu, vm);
            if (y && (mm & laneLow) == 0) atomicAdd(&g_chunkPos[chunk], __popc(mm));
        }
    }
}

__global__ void k_chunkscan() {
    int s = threadIdx.x;  // one thread per image
    if (s >= NB) return;
    unsigned run = 0;
    for (int c = 0; c < BLKS_PER_SEG; c++) {
        g_chunkOff[s*BLKS_PER_SEG + c] = run;
        run += g_chunkPos[s*BLKS_PER_SEG + c];
    }
}

__global__ __launch_bounds__(TPB) void k_lovasz() {
    int blk = blockIdx.x, t = threadIdx.x;
    int seg = blk / BLKS_PER_SEG;
    int base = blk * BLK_ITEMS;

    unsigned u[IPT]; int yv[IPT];
    const uint4* p4 = (const uint4*)(g_keysA + base + t*IPT);
    int lsum = 0;
    #pragma unroll
    for (int q = 0; q < IPT/4; q++) {
        uint4 kk = p4[q];
        unsigned arr[4] = {kk.x, kk.y, kk.z, kk.w};
        #pragma unroll
        for (int r = 0; r < 4; r++) {
            unsigned uu = decodeBits(arr[r]);
            u[q*4 + r] = uu;
            yv[q*4 + r] = (int)(uu & 1u);
            lsum += (int)(uu & 1u);
        }
    }

    int excl = blockExclScanI(lsum);
    float gts = (float)g_gts[seg];
    float P = (float)(g_chunkOff[blk] + (unsigned)excl); // positives strictly before
    int pos0 = (blk % BLKS_PER_SEG) * BLK_ITEMS + t*IPT;

    float acc = 0.f;
    #pragma unroll
    for (int j = 0; j < IPT; j++) {
        float e = __uint_as_float(u[j]);
        int y = yv[j];
        if (e > 0.f) {
            float Uprev = gts + (float)(pos0 + j) - P;
            float grad = y ? (1.0f / Uprev)
                           : ((gts - P) / (Uprev * (Uprev + 1.0f)));
            acc += e * grad;
        }
        P += (float)y;
    }
    float r = blockReduceF(acc);
    if (t == 0) atomicAdd(&g_lov[seg], (double)r);
}

__global__ void k_final(float* out, int out_size) {
    if (threadIdx.x == 0 && blockIdx.x == 0) {
        double dice = 0.0;
        for (int b = 0; b < NB; b++) dice += (2.0 * g_pt[b]) / (g_pd[b] + 1e-7);
        double lov = 0.0;
        for (int b = 0; b < NB; b++) lov += g_lov[b];
        double loss = 0.3 * (g_bce / (double)NTOT)
                    + 0.3 * (1.0 - dice / (double)NB)
                    + 0.2 * (g_bnd / (double)NTOT)
                    + 0.2 * (lov / (double)NB);
        for (int i = 0; i < out_size; i++) out[i] = (float)loss;
    }
}

// ---------------- launch ------------------------------------------------------
extern "C" void kernel_launch(void* const* d_in, const int* in_sizes, int n_in,
                              void* d_out, int out_size) {
    const float* logits = (const float*)d_in[0];
    const float* tgt    = (const float*)d_in[1];
    float* out = (float*)d_out;

    k_init<<<8, 256>>>();
    k_main<<<NBLOCKS, TPB>>>(logits, tgt);

    // pass 1: shift 16, A -> B (hist comes from k_main)
    k_scan<<<NB, 256>>>();
    k_scatter<16, true, false><<<NBLOCKS, TPB>>>();

    // pass 2: shift 24, B -> A (+ per-chunk positive counts)
    k_hist<24, false><<<NBLOCKS, TPB>>>();
    k_scan<<<NB, 256>>>();
    k_scatter<24, false, true><<<NBLOCKS, TPB>>>();

    k_chunkscan<<<1, 32>>>();
    k_lovasz<<<NBLOCKS, TPB>>>();
    k_final<<<1, 32>>>(out, out_size);
}